// round 2
// baseline (speedup 1.0000x reference)
#include <cuda_runtime.h>

#define NV 10000
#define NR 8
#define NC 64
#define NU 64

#define ROWS 128           // output rows per CTA
#define NTHREADS 256
#define APAD 68            // floats per A row (64 + 4 pad; conflict-free, 16B-aligned stride)

#define SA_FLOATS (ROWS * APAD)      // 8704 per buffer
#define SK_FLOATS (NC * NU)          // 4096 per buffer
#define SMEM_BYTES ((2 * SA_FLOATS + 2 * SK_FLOATS) * 4)   // 102400 B

// zero page for invalid (-1) gather slots — device globals are zero-init
__device__ __align__(16) float g_zero[64] = {};

// ---- packed fp32x2 FMA (sm_103a FFMA2, PTX-only) ----
__device__ __forceinline__ unsigned long long fma2(unsigned long long a,
                                                   unsigned long long b,
                                                   unsigned long long c) {
    unsigned long long d;
    asm("fma.rn.f32x2 %0, %1, %2, %3;" : "=l"(d) : "l"(a), "l"(b), "l"(c));
    return d;
}
__device__ __forceinline__ unsigned long long bcast2(float x) {
    unsigned long long d;
    asm("mov.b64 %0, {%1, %1};" : "=l"(d) : "f"(x));
    return d;
}
__device__ __forceinline__ float2 unpack2(unsigned long long v) {
    float2 f;
    asm("mov.b64 {%0, %1}, %2;" : "=f"(f.x), "=f"(f.y) : "l"(v));
    return f;
}

// ---- cp.async helpers ----
__device__ __forceinline__ unsigned cvta_smem(const void* p) {
    unsigned r;
    asm("{ .reg .u64 t; cvta.to.shared.u64 t, %1; cvt.u32.u64 %0, t; }"
        : "=r"(r) : "l"(p));
    return r;
}
__device__ __forceinline__ void cpasync16(unsigned dst, const void* src) {
    asm volatile("cp.async.cg.shared.global [%0], [%1], 16;" :: "r"(dst), "l"(src));
}
#define CP_COMMIT() asm volatile("cp.async.commit_group;" ::: "memory")
#define CP_WAIT(n)  asm volatile("cp.async.wait_group %0;" :: "n"(n) : "memory")

__global__ void __launch_bounds__(NTHREADS, 2)
graphconv_kernel(const float* __restrict__ nodes,
                 const int*   __restrict__ mapping,
                 const float* __restrict__ kern,
                 const float* __restrict__ bias,
                 float*       __restrict__ out)
{
    extern __shared__ float smem[];
    float* sA = smem;                      // [2][ROWS][APAD]
    float* sK = smem + 2 * SA_FLOATS;      // [2][NC][NU]
    const unsigned sA_u = cvta_smem(sA);
    const unsigned sK_u = cvta_smem(sK);

    const int tid  = threadIdx.x;
    const int tx   = tid & 7;              // u-group: u = tx*8 .. tx*8+7
    const int ty   = tid >> 3;             // 0..31: rows ty + 32*i, i=0..3
    const int row0 = blockIdx.x * ROWS;

    // ---- gather role: 2 lanes per row, each covers 128 B ----
    const int grow_l = tid >> 1;           // local row 0..127
    const int lane   = tid & 1;            // half-row selector
    const int grow   = row0 + grow_l;
    const int bV     = (grow / NV) * NV;   // batch base (one division total)
    const float* gz  = g_zero + lane * 32;

    unsigned long long acc[4][4];
#pragma unroll
    for (int i = 0; i < 4; ++i)
#pragma unroll
        for (int p = 0; p < 4; ++p) acc[i][p] = 0ULL;

    // ---- prologue: mapping r=0, issue region-0 gathers, prefetch mapping r=1 ----
    int m_cur = __ldg(mapping + (size_t)grow * NR);
    {
        const float* src = (m_cur >= 0)
            ? nodes + ((size_t)(bV + m_cur) << 6) + lane * 32 : gz;
        unsigned dA = sA_u + (unsigned)(grow_l * APAD + lane * 32) * 4u;
#pragma unroll
        for (int j = 0; j < 8; ++j) cpasync16(dA + j * 16, src + j * 4);
        const float* ks = kern + tid * 16;     // region 0
        unsigned dK = sK_u + (unsigned)(tid * 16) * 4u;
#pragma unroll
        for (int j = 0; j < 4; ++j) cpasync16(dK + j * 16, ks + j * 4);
        CP_COMMIT();
    }
    int m_nxt = __ldg(mapping + (size_t)grow * NR + 1);

#pragma unroll 1
    for (int r = 0; r < NR; ++r) {
        const int buf = r & 1;

        // ---- issue gathers for region r+1 into the other buffer ----
        if (r < NR - 1) {
            const int nb = buf ^ 1;
            const float* src = (m_nxt >= 0)
                ? nodes + ((size_t)(bV + m_nxt) << 6) + lane * 32 : gz;
            unsigned dA = sA_u + (unsigned)(nb * SA_FLOATS + grow_l * APAD + lane * 32) * 4u;
#pragma unroll
            for (int j = 0; j < 8; ++j) cpasync16(dA + j * 16, src + j * 4);
            const float* ks = kern + (size_t)(r + 1) * SK_FLOATS + tid * 16;
            unsigned dK = sK_u + (unsigned)(nb * SK_FLOATS + tid * 16) * 4u;
#pragma unroll
            for (int j = 0; j < 4; ++j) cpasync16(dK + j * 16, ks + j * 4);
            CP_COMMIT();
            if (r < NR - 2) m_nxt = __ldg(mapping + (size_t)grow * NR + r + 2);
        }

        // ---- wait for region r's data ----
        if (r < NR - 1) CP_WAIT(1); else CP_WAIT(0);
        __syncthreads();

        const float* A = sA + buf * SA_FLOATS;
        const float* K = sK + buf * SK_FLOATS;

        // ---- accumulate, k batched by 4 ----
#pragma unroll 2
        for (int kb = 0; kb < NC; kb += 4) {
            float4 av[4];
#pragma unroll
            for (int i = 0; i < 4; ++i)
                av[i] = *(const float4*)(A + (ty + 32 * i) * APAD + kb);
#pragma unroll
            for (int kk = 0; kk < 4; ++kk) {
                const ulonglong2* kp =
                    (const ulonglong2*)(K + (kb + kk) * NU + tx * 8);
                ulonglong2 k0 = kp[0];
                ulonglong2 k1 = kp[1];
#pragma unroll
                for (int i = 0; i < 4; ++i) {
                    unsigned long long a2 =
                        bcast2(((const float*)&av[i])[kk]);
                    acc[i][0] = fma2(a2, k0.x, acc[i][0]);
                    acc[i][1] = fma2(a2, k0.y, acc[i][1]);
                    acc[i][2] = fma2(a2, k1.x, acc[i][2]);
                    acc[i][3] = fma2(a2, k1.y, acc[i][3]);
                }
            }
        }
        __syncthreads();   // done reading buf before it is refilled next iter
    }

    // ---- epilogue: bias + relu, vectorized stores ----
    const float4* bg = (const float4*)bias;
    float4 b0 = bg[tx * 2];
    float4 b1 = bg[tx * 2 + 1];

#pragma unroll
    for (int i = 0; i < 4; ++i) {
        int orow = row0 + ty + 32 * i;
        float2 f0 = unpack2(acc[i][0]);
        float2 f1 = unpack2(acc[i][1]);
        float2 f2 = unpack2(acc[i][2]);
        float2 f3 = unpack2(acc[i][3]);
        float4 o0, o1;
        o0.x = fmaxf(f0.x + b0.x, 0.f);
        o0.y = fmaxf(f0.y + b0.y, 0.f);
        o0.z = fmaxf(f1.x + b0.z, 0.f);
        o0.w = fmaxf(f1.y + b0.w, 0.f);
        o1.x = fmaxf(f2.x + b1.x, 0.f);
        o1.y = fmaxf(f2.y + b1.y, 0.f);
        o1.z = fmaxf(f3.x + b1.z, 0.f);
        o1.w = fmaxf(f3.y + b1.w, 0.f);
        float4* op = (float4*)(out + (size_t)orow * NU + tx * 8);
        op[0] = o0;
        op[1] = o1;
    }
}

extern "C" void kernel_launch(void* const* d_in, const int* in_sizes, int n_in,
                              void* d_out, int out_size) {
    (void)in_sizes; (void)n_in; (void)out_size;
    const float* nodes   = (const float*)d_in[0];
    const int*   mapping = (const int*)d_in[1];
    const float* kern    = (const float*)d_in[2];
    const float* bias    = (const float*)d_in[3];
    float*       out     = (float*)d_out;

    cudaFuncSetAttribute(graphconv_kernel,
                         cudaFuncAttributeMaxDynamicSharedMemorySize, SMEM_BYTES);

    int grid = (16 * NV) / ROWS;   // 160000 / 128 = 1250
    graphconv_kernel<<<grid, NTHREADS, SMEM_BYTES>>>(nodes, mapping, kern, bias, out);
}

// round 3
// speedup vs baseline: 1.4158x; 1.4158x over previous
#include <cuda_runtime.h>

#define NV 10000
#define NR 8
#define NC 64
#define NU 64

#define ROWS 128           // output rows per CTA
#define NTHREADS 256
#define APAD 68            // floats per A row (64 + 4 pad; conflict-free row stride)

#define SA_FLOATS (ROWS * APAD)      // 8704 per buffer
#define SK_FLOATS (NC * NU)          // 4096 per buffer
#define SMEM_BYTES ((2 * SA_FLOATS + 2 * SK_FLOATS) * 4)   // 102400 B -> 2 CTA/SM

// zero page for invalid (-1) gather slots — device globals are zero-init
__device__ __align__(16) float g_zero[64] = {};

// ---- packed fp32x2 FMA (sm_103a FFMA2, PTX-only) ----
__device__ __forceinline__ unsigned long long fma2(unsigned long long a,
                                                   unsigned long long b,
                                                   unsigned long long c) {
    unsigned long long d;
    asm("fma.rn.f32x2 %0, %1, %2, %3;" : "=l"(d) : "l"(a), "l"(b), "l"(c));
    return d;
}
__device__ __forceinline__ unsigned long long bcast2(float x) {
    unsigned long long d;
    asm("mov.b64 %0, {%1, %1};" : "=l"(d) : "f"(x));
    return d;
}
__device__ __forceinline__ float2 unpack2(unsigned long long v) {
    float2 f;
    asm("mov.b64 {%0, %1}, %2;" : "=f"(f.x), "=f"(f.y) : "l"(v));
    return f;
}

// ---- cp.async helpers ----
__device__ __forceinline__ unsigned cvta_smem(const void* p) {
    unsigned r;
    asm("{ .reg .u64 t; cvta.to.shared.u64 t, %1; cvt.u32.u64 %0, t; }"
        : "=r"(r) : "l"(p));
    return r;
}
__device__ __forceinline__ void cpasync16(unsigned dst, const void* src) {
    asm volatile("cp.async.cg.shared.global [%0], [%1], 16;" :: "r"(dst), "l"(src));
}
#define CP_COMMIT() asm volatile("cp.async.commit_group;" ::: "memory")
#define CP_WAIT(n)  asm volatile("cp.async.wait_group %0;" :: "n"(n) : "memory")

__global__ void __launch_bounds__(NTHREADS, 2)
graphconv_kernel(const float* __restrict__ nodes,
                 const int*   __restrict__ mapping,
                 const float* __restrict__ kern,
                 const float* __restrict__ bias,
                 float*       __restrict__ out)
{
    extern __shared__ float smem[];
    float* sA = smem;                      // [2][ROWS][APAD]
    float* sK = smem + 2 * SA_FLOATS;      // [2][NC][NU]
    const unsigned sA_u = cvta_smem(sA);
    const unsigned sK_u = cvta_smem(sK);

    const int tid  = threadIdx.x;
    const int tx   = tid & 15;             // u-group: u = tx*4 .. tx*4+3 (warp spans all 32 banks)
    const int ty   = tid >> 4;             // 0..15: rows ty + 16*i, i=0..7
    const int row0 = blockIdx.x * ROWS;

    // ---- gather role: 2 lanes per row, each covers 128 B ----
    const int grow_l = tid >> 1;           // local row 0..127
    const int lane   = tid & 1;            // half-row selector
    const int grow   = row0 + grow_l;
    const int bV     = (grow / NV) * NV;   // batch base (one division total)
    const float* gz  = g_zero + lane * 32;

    unsigned long long acc[8][2];
#pragma unroll
    for (int i = 0; i < 8; ++i) { acc[i][0] = 0ULL; acc[i][1] = 0ULL; }

    // ---- prologue: issue region-0 gathers + K, prefetch mapping r=1 ----
    int m_cur = __ldg(mapping + (size_t)grow * NR);
    {
        const float* src = (m_cur >= 0)
            ? nodes + ((size_t)(bV + m_cur) << 6) + lane * 32 : gz;
        unsigned dA = sA_u + (unsigned)(grow_l * APAD + lane * 32) * 4u;
#pragma unroll
        for (int j = 0; j < 8; ++j) cpasync16(dA + j * 16, src + j * 4);
        const float* ks = kern + tid * 16;           // region 0, 16 floats/thread
        unsigned dK = sK_u + (unsigned)(tid * 16) * 4u;
#pragma unroll
        for (int j = 0; j < 4; ++j) cpasync16(dK + j * 16, ks + j * 4);
        CP_COMMIT();
    }
    int m_nxt = __ldg(mapping + (size_t)grow * NR + 1);

#pragma unroll 1
    for (int r = 0; r < NR; ++r) {
        const int buf = r & 1;

        // ---- issue gathers for region r+1 into the other buffer ----
        if (r < NR - 1) {
            const int nb = buf ^ 1;
            const float* src = (m_nxt >= 0)
                ? nodes + ((size_t)(bV + m_nxt) << 6) + lane * 32 : gz;
            unsigned dA = sA_u + (unsigned)(nb * SA_FLOATS + grow_l * APAD + lane * 32) * 4u;
#pragma unroll
            for (int j = 0; j < 8; ++j) cpasync16(dA + j * 16, src + j * 4);
            const float* ks = kern + (size_t)(r + 1) * SK_FLOATS + tid * 16;
            unsigned dK = sK_u + (unsigned)(nb * SK_FLOATS + tid * 16) * 4u;
#pragma unroll
            for (int j = 0; j < 4; ++j) cpasync16(dK + j * 16, ks + j * 4);
            CP_COMMIT();
            if (r < NR - 2) m_nxt = __ldg(mapping + (size_t)grow * NR + r + 2);
        }

        // ---- wait for region r's data ----
        if (r < NR - 1) { CP_WAIT(1); } else { CP_WAIT(0); }
        __syncthreads();

        const float* A = sA + buf * SA_FLOATS + ty * APAD;
        const float* K = sK + buf * SK_FLOATS + tx * 4;

        // ---- accumulate: per 4k-block: 4 K-LDS.128 + 8 A-LDS.128 + 64 FFMA2 ----
#pragma unroll 4
        for (int kb = 0; kb < NC; kb += 4) {
            ulonglong2 kq[4];
#pragma unroll
            for (int kk = 0; kk < 4; ++kk)
                kq[kk] = *(const ulonglong2*)(K + (kb + kk) * NU);
#pragma unroll
            for (int i = 0; i < 8; ++i) {
                float4 a = *(const float4*)(A + i * 16 * APAD + kb);
                unsigned long long a0 = bcast2(a.x);
                unsigned long long a1 = bcast2(a.y);
                unsigned long long a2 = bcast2(a.z);
                unsigned long long a3 = bcast2(a.w);
                acc[i][0] = fma2(a0, kq[0].x, acc[i][0]);
                acc[i][1] = fma2(a0, kq[0].y, acc[i][1]);
                acc[i][0] = fma2(a1, kq[1].x, acc[i][0]);
                acc[i][1] = fma2(a1, kq[1].y, acc[i][1]);
                acc[i][0] = fma2(a2, kq[2].x, acc[i][0]);
                acc[i][1] = fma2(a2, kq[2].y, acc[i][1]);
                acc[i][0] = fma2(a3, kq[3].x, acc[i][0]);
                acc[i][1] = fma2(a3, kq[3].y, acc[i][1]);
            }
        }
        __syncthreads();   // done reading buf before it is refilled
    }

    // ---- epilogue: bias + relu, one float4 store per row ----
    float4 bv4 = ((const float4*)bias)[tx];

#pragma unroll
    for (int i = 0; i < 8; ++i) {
        int orow = row0 + ty + 16 * i;
        float2 f0 = unpack2(acc[i][0]);
        float2 f1 = unpack2(acc[i][1]);
        float4 o;
        o.x = fmaxf(f0.x + bv4.x, 0.f);
        o.y = fmaxf(f0.y + bv4.y, 0.f);
        o.z = fmaxf(f1.x + bv4.z, 0.f);
        o.w = fmaxf(f1.y + bv4.w, 0.f);
        *(float4*)(out + (size_t)orow * NU + tx * 4) = o;
    }
}

extern "C" void kernel_launch(void* const* d_in, const int* in_sizes, int n_in,
                              void* d_out, int out_size) {
    (void)in_sizes; (void)n_in; (void)out_size;
    const float* nodes   = (const float*)d_in[0];
    const int*   mapping = (const int*)d_in[1];
    const float* kern    = (const float*)d_in[2];
    const float* bias    = (const float*)d_in[3];
    float*       out     = (float*)d_out;

    cudaFuncSetAttribute(graphconv_kernel,
                         cudaFuncAttributeMaxDynamicSharedMemorySize, SMEM_BYTES);

    int grid = (16 * NV) / ROWS;   // 1250
    graphconv_kernel<<<grid, NTHREADS, SMEM_BYTES>>>(nodes, mapping, kern, bias, out);
}

// round 5
// speedup vs baseline: 2.6844x; 1.8960x over previous
#include <cuda_runtime.h>
#include <cstdint>

#define NV 10000
#define NR 8
#define NC 64
#define NU 64

#define ROWS 128
#define NTHREADS 256
#define APAD 68                       // fp32 row stride (16B-aligned, conflict-free)
#define BPAD 68

#define SA_FLOATS (ROWS * APAD)       // 8704
#define SB_FLOATS (NC * BPAD)         // 4352
#define SMEM_BYTES ((2*SA_FLOATS + 2*SB_FLOATS) * 4)   // 104448 -> 2 CTA/SM

// zero row for invalid (-1) gather slots
__device__ __align__(16) float g_zero[64] = {};

// ---------------- helpers ----------------
__device__ __forceinline__ unsigned cvta_smem(const void* p) {
    unsigned r;
    asm("{ .reg .u64 t; cvta.to.shared.u64 t, %1; cvt.u32.u64 %0, t; }"
        : "=r"(r) : "l"(p));
    return r;
}
__device__ __forceinline__ void cpasync16(unsigned dst, const void* src) {
    asm volatile("cp.async.cg.shared.global [%0], [%1], 16;" :: "r"(dst), "l"(src));
}
#define CP_COMMIT() asm volatile("cp.async.commit_group;" ::: "memory")
#define CP_WAIT(n)  asm volatile("cp.async.wait_group %0;" :: "n"(n) : "memory")

__device__ __forceinline__ unsigned cvt_tf32(float f) {
    unsigned t;
    asm("cvt.rna.tf32.f32 %0, %1;" : "=r"(t) : "f"(f));
    return t;
}
__device__ __forceinline__ void ldsm_x4(unsigned addr, unsigned& r0, unsigned& r1,
                                        unsigned& r2, unsigned& r3) {
    asm volatile("ldmatrix.sync.aligned.m8n8.x4.shared.b16 {%0,%1,%2,%3}, [%4];"
                 : "=r"(r0), "=r"(r1), "=r"(r2), "=r"(r3) : "r"(addr));
}
__device__ __forceinline__ void mma_tf32(float& d0, float& d1, float& d2, float& d3,
                                         unsigned a0, unsigned a1, unsigned a2, unsigned a3,
                                         unsigned b0, unsigned b1) {
    asm volatile("mma.sync.aligned.m16n8k8.row.col.f32.tf32.tf32.f32 "
                 "{%0,%1,%2,%3}, {%4,%5,%6,%7}, {%8,%9}, {%0,%1,%2,%3};"
                 : "+f"(d0), "+f"(d1), "+f"(d2), "+f"(d3)
                 : "r"(a0), "r"(a1), "r"(a2), "r"(a3), "r"(b0), "r"(b1));
}

__global__ void __launch_bounds__(NTHREADS, 2)
graphconv_mma(const float* __restrict__ nodes,
              const int*   __restrict__ mapping,
              const float* __restrict__ kern,
              const float* __restrict__ bias,
              float*       __restrict__ out)
{
    extern __shared__ float smem[];
    float* sA = smem;                       // [2][ROWS][APAD]
    float* sB = smem + 2 * SA_FLOATS;       // [2][NC][BPAD]
    const unsigned sA_u = cvta_smem(sA);

    const int tid  = threadIdx.x;
    const int row0 = blockIdx.x * ROWS;

    const int wid = tid >> 5;
    const int l   = tid & 31;
    const int mg  = wid & 3;                // m-group: rows mg*32 .. mg*32+31
    const int ng  = wid >> 2;               // n-group: u  ng*32 .. ng*32+31

    // ---- gather roles: 2 lanes per row, 8 x 16B chunks each ----
    const int gm   = tid >> 1;              // local row 0..127
    const int gl   = tid & 1;
    const int grow = row0 + gm;
    const int bV   = (grow / NV) * NV;

    // ---- A fragment ldmatrix lane address (fixed part) ----
    // matrix quadrant: row = mbase + (l&15), col k-offset = (l>>4)*4
    const unsigned a_lane_rel =
        (unsigned)(((mg * 32 + (l & 15)) * APAD + ((l >> 4) << 2)) * 4);

    // ---- B fragment scalar offsets (fixed part) ----
    // b0 = B[k0 + (l&3)][ng*32 + nt*8 + (l>>2)]
    const int b_lane_rel = (l & 3) * BPAD + ng * 32 + (l >> 2);

    float d[2][4][4];
#pragma unroll
    for (int mt = 0; mt < 2; ++mt)
#pragma unroll
        for (int nt = 0; nt < 4; ++nt)
#pragma unroll
            for (int q = 0; q < 4; ++q) d[mt][nt][q] = 0.f;

    // ---- prologue: region 0 A+B via cp.async ----
    int m_cur = __ldg(mapping + (size_t)grow * NR);
    {
        const float* src = (m_cur >= 0)
            ? nodes + ((size_t)(bV + m_cur) << 6) + gl * 32 : g_zero;
        unsigned dA = sA_u + (unsigned)((gm * APAD) * 4 + gl * 128);
#pragma unroll
        for (int j = 0; j < 8; ++j) cpasync16(dA + j * 16, src + j * 4);
        // B: 1024 16B-chunks, 4 per thread
        unsigned sB_u = sA_u + 2 * SA_FLOATS * 4;
#pragma unroll
        for (int i = 0; i < 4; ++i) {
            const int c = tid + i * NTHREADS;
            unsigned dB = sB_u + (unsigned)(((c >> 4) * BPAD + (c & 15) * 4) * 4);
            cpasync16(dB, kern + (size_t)(c >> 4) * NU + (c & 15) * 4);
        }
        CP_COMMIT();
    }
    int m_nxt = __ldg(mapping + (size_t)grow * NR + 1);

#pragma unroll 1
    for (int r = 0; r < NR; ++r) {
        const int buf = r & 1;

        // ---- issue region r+1 into the other buffer ----
        if (r < NR - 1) {
            const int nb = buf ^ 1;
            const float* src = (m_nxt >= 0)
                ? nodes + ((size_t)(bV + m_nxt) << 6) + gl * 32 : g_zero;
            unsigned dA = sA_u + (unsigned)((nb * SA_FLOATS + gm * APAD) * 4 + gl * 128);
#pragma unroll
            for (int j = 0; j < 8; ++j) cpasync16(dA + j * 16, src + j * 4);
            unsigned sB_u = sA_u + (unsigned)((2 * SA_FLOATS + nb * SB_FLOATS) * 4);
            const float* kg = kern + (size_t)(r + 1) * (NC * NU);
#pragma unroll
            for (int i = 0; i < 4; ++i) {
                const int c = tid + i * NTHREADS;
                unsigned dB = sB_u + (unsigned)(((c >> 4) * BPAD + (c & 15) * 4) * 4);
                cpasync16(dB, kg + (size_t)(c >> 4) * NU + (c & 15) * 4);
            }
            CP_COMMIT();
            if (r < NR - 2) m_nxt = __ldg(mapping + (size_t)grow * NR + r + 2);
        }

        if (r < NR - 1) { CP_WAIT(1); } else { CP_WAIT(0); }
        __syncthreads();

        const unsigned aaddr0 = sA_u + (unsigned)(buf * SA_FLOATS * 4) + a_lane_rel;
        const float*   Bb     = sB + buf * SB_FLOATS + b_lane_rel;

        // ---- 8 k-steps of m16n8k8 tf32 ----
#pragma unroll
        for (int ks = 0; ks < 8; ++ks) {
            const int k0 = ks * 8;
            unsigned a[2][4];
#pragma unroll
            for (int mt = 0; mt < 2; ++mt) {
                ldsm_x4(aaddr0 + (unsigned)((mt * 16 * APAD + k0) * 4),
                        a[mt][0], a[mt][1], a[mt][2], a[mt][3]);
#pragma unroll
                for (int q = 0; q < 4; ++q)
                    a[mt][q] = cvt_tf32(__uint_as_float(a[mt][q]));
            }
            unsigned b[4][2];
            const float* Bk = Bb + k0 * BPAD;
#pragma unroll
            for (int nt = 0; nt < 4; ++nt) {
                b[nt][0] = cvt_tf32(Bk[nt * 8]);
                b[nt][1] = cvt_tf32(Bk[4 * BPAD + nt * 8]);
            }
#pragma unroll
            for (int mt = 0; mt < 2; ++mt)
#pragma unroll
                for (int nt = 0; nt < 4; ++nt)
                    mma_tf32(d[mt][nt][0], d[mt][nt][1], d[mt][nt][2], d[mt][nt][3],
                             a[mt][0], a[mt][1], a[mt][2], a[mt][3],
                             b[nt][0], b[nt][1]);
        }
        __syncthreads();   // all warps done reading buf before it is refilled
    }

    // ---- epilogue: bias + relu + STG.64 straight from fragments ----
#pragma unroll
    for (int nt = 0; nt < 4; ++nt) {
        const int u0 = ng * 32 + nt * 8 + 2 * (l & 3);
        float2 bv = *(const float2*)(bias + u0);
#pragma unroll
        for (int mt = 0; mt < 2; ++mt) {
            const int rA = row0 + mg * 32 + mt * 16 + (l >> 2);
            float2 o0, o1;
            o0.x = fmaxf(d[mt][nt][0] + bv.x, 0.f);
            o0.y = fmaxf(d[mt][nt][1] + bv.y, 0.f);
            o1.x = fmaxf(d[mt][nt][2] + bv.x, 0.f);
            o1.y = fmaxf(d[mt][nt][3] + bv.y, 0.f);
            *(float2*)(out + (size_t)rA * NU + u0)       = o0;
            *(float2*)(out + (size_t)(rA + 8) * NU + u0) = o1;
        }
    }
}

extern "C" void kernel_launch(void* const* d_in, const int* in_sizes, int n_in,
                              void* d_out, int out_size) {
    (void)in_sizes; (void)n_in; (void)out_size;
    const float* nodes   = (const float*)d_in[0];
    const int*   mapping = (const int*)d_in[1];
    const float* kern    = (const float*)d_in[2];
    const float* bias    = (const float*)d_in[3];
    float*       out     = (float*)d_out;

    cudaFuncSetAttribute(graphconv_mma,
                         cudaFuncAttributeMaxDynamicSharedMemorySize, SMEM_BYTES);

    int grid = (16 * NV) / ROWS;   // 1250
    graphconv_mma<<<grid, NTHREADS, SMEM_BYTES>>>(nodes, mapping, kern, bias, out);
}

// round 6
// speedup vs baseline: 2.7142x; 1.0111x over previous
#include <cuda_runtime.h>
#include <cstdint>

#define NV 10000
#define NR 8
#define NC 64
#define NU 64

#define ROWS 128
#define NTHREADS 256
#define APAD 68                       // A fp32 row stride (conflict-free)

#define SA_FLOATS (ROWS * APAD)       // 8704 per buffer
#define SB_FLOATS 4096                // paired tf32 B: 8ks*64u*4kk*2 floats (16KB)
#define SMEM_BYTES ((2*SA_FLOATS + 2*SB_FLOATS) * 4)   // 102400 -> 2 CTA/SM

// zero row for invalid (-1) gather slots
__device__ __align__(16) float g_zero[64] = {};

// ---------------- helpers ----------------
__device__ __forceinline__ unsigned cvta_smem(const void* p) {
    unsigned r;
    asm("{ .reg .u64 t; cvta.to.shared.u64 t, %1; cvt.u32.u64 %0, t; }"
        : "=r"(r) : "l"(p));
    return r;
}
__device__ __forceinline__ void cpasync16(unsigned dst, const void* src) {
    asm volatile("cp.async.cg.shared.global [%0], [%1], 16;" :: "r"(dst), "l"(src));
}
#define CP_COMMIT() asm volatile("cp.async.commit_group;" ::: "memory")
#define CP_WAIT(n)  asm volatile("cp.async.wait_group %0;" :: "n"(n) : "memory")

__device__ __forceinline__ unsigned cvt_tf32(float f) {
    unsigned t;
    asm("cvt.rna.tf32.f32 %0, %1;" : "=r"(t) : "f"(f));
    return t;
}
__device__ __forceinline__ void ldsm_x4(unsigned addr, unsigned& r0, unsigned& r1,
                                        unsigned& r2, unsigned& r3) {
    asm volatile("ldmatrix.sync.aligned.m8n8.x4.shared.b16 {%0,%1,%2,%3}, [%4];"
                 : "=r"(r0), "=r"(r1), "=r"(r2), "=r"(r3) : "r"(addr));
}
__device__ __forceinline__ void mma_tf32(float& d0, float& d1, float& d2, float& d3,
                                         unsigned a0, unsigned a1, unsigned a2, unsigned a3,
                                         unsigned b0, unsigned b1) {
    asm volatile("mma.sync.aligned.m16n8k8.row.col.f32.tf32.tf32.f32 "
                 "{%0,%1,%2,%3}, {%4,%5,%6,%7}, {%8,%9}, {%0,%1,%2,%3};"
                 : "+f"(d0), "+f"(d1), "+f"(d2), "+f"(d3)
                 : "r"(a0), "r"(a1), "r"(a2), "r"(a3), "r"(b0), "r"(b1));
}

__global__ void __launch_bounds__(NTHREADS, 2)
graphconv_mma(const float* __restrict__ nodes,
              const int*   __restrict__ mapping,
              const float* __restrict__ kern,
              const float* __restrict__ bias,
              float*       __restrict__ out)
{
    extern __shared__ float smem[];
    float* sA = smem;                       // [2][ROWS][APAD]
    float* sB = smem + 2 * SA_FLOATS;       // [2][2048] float2 (paired tf32)
    const unsigned sA_u = cvta_smem(sA);

    const int tid  = threadIdx.x;
    const int row0 = blockIdx.x * ROWS;

    const int wid = tid >> 5;
    const int l   = tid & 31;
    const int mg  = wid & 3;                // m-group: rows mg*32 .. mg*32+31
    const int ng  = wid >> 2;               // n-group: u  ng*32 .. ng*32+31

    // ---- gather roles: 2 lanes per row, 8 x 16B chunks each ----
    const int gm   = tid >> 1;              // local row 0..127
    const int gl   = tid & 1;
    const int grow = row0 + gm;
    const int bV   = (grow / NV) * NV;

    // ---- A fragment ldmatrix lane address (fixed part) ----
    const unsigned a_lane_rel =
        (unsigned)(((mg * 32 + (l & 15)) * APAD + ((l >> 4) << 2)) * 4);

    // ---- B fragment float2-index (fixed part): conflict-free LDS.64 ----
    const int b_lane_rel = ng * 128 + (l >> 2) * 4 + (l & 3);

    float d[2][4][4];
#pragma unroll
    for (int mt = 0; mt < 2; ++mt)
#pragma unroll
        for (int nt = 0; nt < 4; ++nt)
#pragma unroll
            for (int q = 0; q < 4; ++q) d[mt][nt][q] = 0.f;

    // ---- prologue: region 0 A (cp.async) + B (LDG->cvt->STS paired tf32) ----
    int m_cur = __ldg(mapping + (size_t)grow * NR);
    {
        const float* src = (m_cur >= 0)
            ? nodes + ((size_t)(bV + m_cur) << 6) + gl * 32 : g_zero;
        unsigned dA = sA_u + (unsigned)((gm * APAD) * 4 + gl * 128);
#pragma unroll
        for (int j = 0; j < 8; ++j) cpasync16(dA + j * 16, src + j * 4);
        CP_COMMIT();

        uint2* Bn = (uint2*)sB;
#pragma unroll
        for (int i = 0; i < 8; ++i) {
            const int j  = tid + i * NTHREADS;   // float2 index 0..2047
            const int k0 = ((j >> 8) << 3) + (j & 3);
            const int u  = (j >> 2) & 63;
            uint2 t;
            t.x = cvt_tf32(__ldg(kern + k0 * NU + u));
            t.y = cvt_tf32(__ldg(kern + (k0 + 4) * NU + u));
            Bn[j] = t;
        }
    }
    int m_nxt = __ldg(mapping + (size_t)grow * NR + 1);

#pragma unroll 1
    for (int r = 0; r < NR; ++r) {
        const int buf = r & 1;

        // ---- stage region r+1 into the other buffer ----
        if (r < NR - 1) {
            const int nb = buf ^ 1;
            const float* src = (m_nxt >= 0)
                ? nodes + ((size_t)(bV + m_nxt) << 6) + gl * 32 : g_zero;
            unsigned dA = sA_u + (unsigned)((nb * SA_FLOATS + gm * APAD) * 4 + gl * 128);
#pragma unroll
            for (int j = 0; j < 8; ++j) cpasync16(dA + j * 16, src + j * 4);
            CP_COMMIT();

            const float* kg = kern + (size_t)(r + 1) * (NC * NU);
            uint2* Bn = (uint2*)(sB + nb * SB_FLOATS);
#pragma unroll
            for (int i = 0; i < 8; ++i) {
                const int j  = tid + i * NTHREADS;
                const int k0 = ((j >> 8) << 3) + (j & 3);
                const int u  = (j >> 2) & 63;
                uint2 t;
                t.x = cvt_tf32(__ldg(kg + k0 * NU + u));
                t.y = cvt_tf32(__ldg(kg + (k0 + 4) * NU + u));
                Bn[j] = t;
            }
            if (r < NR - 2) m_nxt = __ldg(mapping + (size_t)grow * NR + r + 2);
        }

        if (r < NR - 1) { CP_WAIT(1); } else { CP_WAIT(0); }
        __syncthreads();

        const unsigned aaddr0 = sA_u + (unsigned)(buf * SA_FLOATS * 4) + a_lane_rel;
        const uint2*   Bb     = (const uint2*)(sB + buf * SB_FLOATS) + b_lane_rel;

        // ---- 8 k-steps, register double-buffered fragments ----
        unsigned a[2][2][4];
        uint2    b[2][4];

        // load ks=0 fragments
#pragma unroll
        for (int mt = 0; mt < 2; ++mt) {
            ldsm_x4(aaddr0 + (unsigned)((mt * 16 * APAD) * 4),
                    a[0][mt][0], a[0][mt][1], a[0][mt][2], a[0][mt][3]);
#pragma unroll
            for (int q = 0; q < 4; ++q)
                a[0][mt][q] = cvt_tf32(__uint_as_float(a[0][mt][q]));
        }
#pragma unroll
        for (int nt = 0; nt < 4; ++nt) b[0][nt] = Bb[nt * 32];

#pragma unroll
        for (int ks = 0; ks < 8; ++ks) {
            const int cur = ks & 1, nxt = cur ^ 1;
            if (ks < 7) {
                const int k1 = (ks + 1) * 8;
#pragma unroll
                for (int mt = 0; mt < 2; ++mt) {
                    ldsm_x4(aaddr0 + (unsigned)((mt * 16 * APAD + k1) * 4),
                            a[nxt][mt][0], a[nxt][mt][1], a[nxt][mt][2], a[nxt][mt][3]);
#pragma unroll
                    for (int q = 0; q < 4; ++q)
                        a[nxt][mt][q] = cvt_tf32(__uint_as_float(a[nxt][mt][q]));
                }
#pragma unroll
                for (int nt = 0; nt < 4; ++nt)
                    b[nxt][nt] = Bb[(ks + 1) * 256 + nt * 32];
            }
#pragma unroll
            for (int mt = 0; mt < 2; ++mt)
#pragma unroll
                for (int nt = 0; nt < 4; ++nt)
                    mma_tf32(d[mt][nt][0], d[mt][nt][1], d[mt][nt][2], d[mt][nt][3],
                             a[cur][mt][0], a[cur][mt][1], a[cur][mt][2], a[cur][mt][3],
                             b[cur][nt].x, b[cur][nt].y);
        }
        __syncthreads();   // all warps done reading buf before refill
    }

    // ---- epilogue: bias + relu + STG.64 straight from fragments ----
#pragma unroll
    for (int nt = 0; nt < 4; ++nt) {
        const int u0 = ng * 32 + nt * 8 + 2 * (l & 3);
        float2 bv = *(const float2*)(bias + u0);
#pragma unroll
        for (int mt = 0; mt < 2; ++mt) {
            const int rA = row0 + mg * 32 + mt * 16 + (l >> 2);
            float2 o0, o1;
            o0.x = fmaxf(d[mt][nt][0] + bv.x, 0.f);
            o0.y = fmaxf(d[mt][nt][1] + bv.y, 0.f);
            o1.x = fmaxf(d[mt][nt][2] + bv.x, 0.f);
            o1.y = fmaxf(d[mt][nt][3] + bv.y, 0.f);
            *(float2*)(out + (size_t)rA * NU + u0)       = o0;
            *(float2*)(out + (size_t)(rA + 8) * NU + u0) = o1;
        }
    }
}

extern "C" void kernel_launch(void* const* d_in, const int* in_sizes, int n_in,
                              void* d_out, int out_size) {
    (void)in_sizes; (void)n_in; (void)out_size;
    const float* nodes   = (const float*)d_in[0];
    const int*   mapping = (const int*)d_in[1];
    const float* kern    = (const float*)d_in[2];
    const float* bias    = (const float*)d_in[3];
    float*       out     = (float*)d_out;

    cudaFuncSetAttribute(graphconv_mma,
                         cudaFuncAttributeMaxDynamicSharedMemorySize, SMEM_BYTES);

    int grid = (16 * NV) / ROWS;   // 1250
    graphconv_mma<<<grid, NTHREADS, SMEM_BYTES>>>(nodes, mapping, kern, bias, out);
}